// round 1
// baseline (speedup 1.0000x reference)
#include <cuda_runtime.h>
#include <cuda_bf16.h>

// Problem constants
#define S_LEN 2048
#define NH    16
#define HD    64
#define BT    64
#define BK    64
#define NTHR  256
#define SCALE 0.1875f   // 1.5 / sqrt(64)

// Shared layout (floats): Qs[64*64] | Ks[64*68] | Vs[64*64] | At[64*64]
#define SMEM_FLOATS (64*64 + 64*68 + 64*64 + 64*64)

__global__ void __launch_bounds__(NTHR, 2)
sb_attn_kernel(const float* __restrict__ qkv, float* __restrict__ out)
{
    extern __shared__ float smem[];
    float* Qs = smem;                  // [64][64], pre-scaled
    float* Ks = Qs + 64 * 64;          // [64][68] padded
    float* Vs = Ks + 64 * 68;          // [64][64]
    float* At = Vs + 64 * 64;          // [64][64]

    // Heavy tiles first (largest t-tile has the most key tiles)
    const int tt   = (int)gridDim.x - 1 - (int)blockIdx.x;
    const int h    = blockIdx.y;
    const int b    = blockIdx.z;
    const int tid  = threadIdx.x;
    const int warp = tid >> 5;
    const int lane = tid & 31;
    const int t0   = tt * BT;

    // ---- Load Q tile (scaled) ----
    #pragma unroll
    for (int i = tid; i < 64 * 16; i += NTHR) {
        int r  = i >> 4;
        int c4 = i & 15;
        const float* p = qkv + (((size_t)b * S_LEN + (t0 + r)) * 3 + 0) * (NH * HD)
                             + h * HD + c4 * 4;
        float4 v = *(const float4*)p;
        float4 w = make_float4(v.x * SCALE, v.y * SCALE, v.z * SCALE, v.w * SCALE);
        *(float4*)&Qs[r * 64 + c4 * 4] = w;
    }

    float  run[8];
    float2 o[8];
    #pragma unroll
    for (int r = 0; r < 8; r++) { run[r] = 0.f; o[r] = make_float2(0.f, 0.f); }

    // ---- Iterate key tiles from diagonal down to 0 (suffix-sum order) ----
    for (int kt = tt; kt >= 0; --kt) {
        __syncthreads();   // previous tile's K/V reads done
        const int s0 = kt * BK;

        // load K and V tiles
        #pragma unroll
        for (int i = tid; i < 64 * 16; i += NTHR) {
            int r  = i >> 4;
            int c4 = i & 15;
            const float* kp = qkv + (((size_t)b * S_LEN + (s0 + r)) * 3 + 1) * (NH * HD)
                                  + h * HD + c4 * 4;
            *(float4*)&Ks[r * 68 + c4 * 4] = *(const float4*)kp;
            *(float4*)&Vs[r * 64 + c4 * 4] = *(const float4*)(kp + NH * HD);
        }
        __syncthreads();

        // ---- Scores: warp owns rows warp*8..+7; lane owns keys lane, lane+32 ----
        float a0[8], a1[8];
        #pragma unroll
        for (int r = 0; r < 8; r++) { a0[r] = 0.f; a1[r] = 0.f; }

        #pragma unroll
        for (int d4 = 0; d4 < 16; d4++) {
            float4 k0 = *(const float4*)&Ks[lane        * 68 + d4 * 4];
            float4 k1 = *(const float4*)&Ks[(lane + 32) * 68 + d4 * 4];
            #pragma unroll
            for (int r = 0; r < 8; r++) {
                float4 q = *(const float4*)&Qs[(warp * 8 + r) * 64 + d4 * 4];
                a0[r] += q.x * k0.x + q.y * k0.y + q.z * k0.z + q.w * k0.w;
                a1[r] += q.x * k1.x + q.y * k1.y + q.z * k1.z + q.w * k1.w;
            }
        }

        // ---- Stick-breaking weights ----
        #pragma unroll
        for (int r = 0; r < 8; r++) {
            const int tg  = t0 + warp * 8 + r;
            const int sg0 = s0 + lane;
            const int sg1 = s0 + lane + 32;
            const float x0 = a0[r], x1 = a1[r];
            const bool m0 = sg0 < tg;
            const bool m1 = sg1 < tg;
            // softplus(x) = max(x,0) + log(1 + exp(-|x|));  logsig(x) = x - softplus(x)
            float p0 = m0 ? (fmaxf(x0, 0.f) + __logf(1.f + __expf(-fabsf(x0)))) : 0.f;
            float p1 = m1 ? (fmaxf(x1, 0.f) + __logf(1.f + __expf(-fabsf(x1)))) : 0.f;

            // reverse inclusive scans over lanes (suffix sums within tile)
            float i0 = p0, i1 = p1;
            #pragma unroll
            for (int off = 1; off < 32; off <<= 1) {
                float u0 = __shfl_down_sync(0xffffffffu, i0, off);
                float u1 = __shfl_down_sync(0xffffffffu, i1, off);
                if (lane + off < 32) { i0 += u0; i1 += u1; }
            }
            const float tot0 = __shfl_sync(0xffffffffu, i0, 0);
            const float tot1 = __shfl_sync(0xffffffffu, i1, 0);
            const float ex1  = i1 - p1;             // suffix-excl within upper half
            const float ex0  = (i0 - p0) + tot1;    // + whole upper half
            const float base = run[r];
            const float att0 = m0 ? __expf(x0 - p0 - base - ex0) : 0.f;
            const float att1 = m1 ? __expf(x1 - p1 - base - ex1) : 0.f;
            At[(warp * 8 + r) * 64 + lane]      = att0;
            At[(warp * 8 + r) * 64 + lane + 32] = att1;
            run[r] = base + tot0 + tot1;
        }
        __syncwarp();   // At rows are per-warp: warp-level ordering suffices

        // ---- AV: lane owns head-dims 2*lane, 2*lane+1 ----
        #pragma unroll
        for (int s4 = 0; s4 < 16; s4++) {
            float2 v0 = *(const float2*)&Vs[(s4 * 4 + 0) * 64 + lane * 2];
            float2 v1 = *(const float2*)&Vs[(s4 * 4 + 1) * 64 + lane * 2];
            float2 v2 = *(const float2*)&Vs[(s4 * 4 + 2) * 64 + lane * 2];
            float2 v3 = *(const float2*)&Vs[(s4 * 4 + 3) * 64 + lane * 2];
            #pragma unroll
            for (int r = 0; r < 8; r++) {
                float4 a = *(const float4*)&At[(warp * 8 + r) * 64 + s4 * 4];
                o[r].x += a.x * v0.x + a.y * v1.x + a.z * v2.x + a.w * v3.x;
                o[r].y += a.x * v0.y + a.y * v1.y + a.z * v2.y + a.w * v3.y;
            }
        }
    }

    // ---- Finalize: remainder term + store ----
    #pragma unroll
    for (int r = 0; r < 8; r++) {
        const int tg  = t0 + warp * 8 + r;
        const float rem = __expf(-run[r]);
        const float* vp = qkv + (((size_t)b * S_LEN + tg) * 3 + 2) * (NH * HD)
                              + h * HD + lane * 2;
        float2 vt = *(const float2*)vp;
        o[r].x += rem * vt.x;
        o[r].y += rem * vt.y;
        float* op = out + (((size_t)b * S_LEN + tg) * NH + h) * HD + lane * 2;
        *(float2*)op = o[r];
    }
}

extern "C" void kernel_launch(void* const* d_in, const int* in_sizes, int n_in,
                              void* d_out, int out_size)
{
    const float* qkv = (const float*)d_in[0];
    float* out = (float*)d_out;

    cudaFuncSetAttribute(sb_attn_kernel,
                         cudaFuncAttributeMaxDynamicSharedMemorySize,
                         SMEM_FLOATS * sizeof(float));

    dim3 grid(S_LEN / BT, NH, 2);   // (32, 16, 2)
    dim3 block(NTHR);
    sb_attn_kernel<<<grid, block, SMEM_FLOATS * sizeof(float)>>>(qkv, out);
}

// round 2
// speedup vs baseline: 1.7580x; 1.7580x over previous
#include <cuda_runtime.h>
#include <cstdint>

#define S_LEN 2048
#define NH    16
#define HD    64
#define NTHR  256
#define SCALE 0.1875f   // 1.5 / sqrt(64)

// smem strides (floats) — chosen for conflict-free fragment loads
#define QS_STRIDE 68
#define KS_STRIDE 68
#define VS_STRIDE 72
#define AT_STRIDE 68

#define SMEM_FLOATS (64*QS_STRIDE + 64*KS_STRIDE + 64*VS_STRIDE + 64*AT_STRIDE + 64)

__device__ __forceinline__ uint32_t f2tf(float x) {
    uint32_t r; asm("cvt.rna.tf32.f32 %0, %1;" : "=r"(r) : "f"(x)); return r;
}

__device__ __forceinline__ void mma_tf32(float& d0, float& d1, float& d2, float& d3,
                                         uint32_t a0, uint32_t a1, uint32_t a2, uint32_t a3,
                                         uint32_t b0, uint32_t b1) {
    asm volatile("mma.sync.aligned.m16n8k8.row.col.f32.tf32.tf32.f32 "
                 "{%0,%1,%2,%3}, {%4,%5,%6,%7}, {%8,%9}, {%0,%1,%2,%3};"
                 : "+f"(d0), "+f"(d1), "+f"(d2), "+f"(d3)
                 : "r"(a0), "r"(a1), "r"(a2), "r"(a3), "r"(b0), "r"(b1));
}

__global__ void __launch_bounds__(NTHR, 2)
sb_attn_kernel(const float* __restrict__ qkv, float* __restrict__ out)
{
    extern __shared__ float smem[];
    float* Qs   = smem;                     // [64][68] tf32 bits (pre-scaled)
    float* Ks   = Qs + 64 * QS_STRIDE;      // [64][68] tf32 bits
    float* Vs   = Ks + 64 * KS_STRIDE;      // [64][72] tf32 bits
    float* At   = Vs + 64 * VS_STRIDE;      // [64][68] scores (f32) then att (tf32 bits)
    float* RemS = At + 64 * AT_STRIDE;      // [64] remainder weights

    const int tt   = (int)gridDim.x - 1 - (int)blockIdx.x;  // heavy tiles first
    const int h    = blockIdx.y;
    const int b    = blockIdx.z;
    const int tid  = threadIdx.x;
    const int warp = tid >> 5;
    const int lane = tid & 31;
    const int t0   = tt * 64;

    // mma partition: warp owns rows m0..m0+15, cols ng*32..ng*32+31 (4 n-tiles of 8)
    const int mb = warp & 3;
    const int ng = warp >> 2;
    const int m0 = mb * 16;
    const int gp = lane >> 2;   // 0..7
    const int qd = lane & 3;    // 0..3

    // ---- Load Q tile (scaled, tf32-rounded) ----
    for (int i = tid; i < 64 * 16; i += NTHR) {
        int r  = i >> 4;
        int c4 = i & 15;
        const float* p = qkv + (((size_t)b * S_LEN + (t0 + r)) * 3 + 0) * (NH * HD)
                             + h * HD + c4 * 4;
        float4 v = *(const float4*)p;
        Qs[r * QS_STRIDE + c4 * 4 + 0] = __uint_as_float(f2tf(v.x * SCALE));
        Qs[r * QS_STRIDE + c4 * 4 + 1] = __uint_as_float(f2tf(v.y * SCALE));
        Qs[r * QS_STRIDE + c4 * 4 + 2] = __uint_as_float(f2tf(v.z * SCALE));
        Qs[r * QS_STRIDE + c4 * 4 + 3] = __uint_as_float(f2tf(v.w * SCALE));
    }

    float run[8];
    float o[4][4];
    #pragma unroll
    for (int r = 0; r < 8; r++) run[r] = 0.f;
    #pragma unroll
    for (int j = 0; j < 4; j++)
        #pragma unroll
        for (int c = 0; c < 4; c++) o[j][c] = 0.f;

    // ---- Key tiles from diagonal down to 0 (suffix-sum order) ----
    for (int kt = tt; kt >= 0; --kt) {
        __syncthreads();   // prev iteration's At/Ks/Vs reads done
        const int s0 = kt * 64;

        for (int i = tid; i < 64 * 16; i += NTHR) {
            int r  = i >> 4;
            int c4 = i & 15;
            const float* kp = qkv + (((size_t)b * S_LEN + (s0 + r)) * 3 + 1) * (NH * HD)
                                  + h * HD + c4 * 4;
            float4 kv = *(const float4*)kp;
            float4 vv = *(const float4*)(kp + NH * HD);
            Ks[r * KS_STRIDE + c4 * 4 + 0] = __uint_as_float(f2tf(kv.x));
            Ks[r * KS_STRIDE + c4 * 4 + 1] = __uint_as_float(f2tf(kv.y));
            Ks[r * KS_STRIDE + c4 * 4 + 2] = __uint_as_float(f2tf(kv.z));
            Ks[r * KS_STRIDE + c4 * 4 + 3] = __uint_as_float(f2tf(kv.w));
            Vs[r * VS_STRIDE + c4 * 4 + 0] = __uint_as_float(f2tf(vv.x));
            Vs[r * VS_STRIDE + c4 * 4 + 1] = __uint_as_float(f2tf(vv.y));
            Vs[r * VS_STRIDE + c4 * 4 + 2] = __uint_as_float(f2tf(vv.z));
            Vs[r * VS_STRIDE + c4 * 4 + 3] = __uint_as_float(f2tf(vv.w));
        }
        __syncthreads();

        // ---- QK^T on tensor pipe: S[m][n] = sum_d Q[m][d] K[n][d] ----
        float d[4][4];
        #pragma unroll
        for (int j = 0; j < 4; j++)
            #pragma unroll
            for (int c = 0; c < 4; c++) d[j][c] = 0.f;

        #pragma unroll
        for (int ks = 0; ks < 8; ks++) {
            const int kc = ks * 8;
            uint32_t a0 = __float_as_uint(Qs[(m0 + gp)     * QS_STRIDE + kc + qd]);
            uint32_t a1 = __float_as_uint(Qs[(m0 + gp + 8) * QS_STRIDE + kc + qd]);
            uint32_t a2 = __float_as_uint(Qs[(m0 + gp)     * QS_STRIDE + kc + qd + 4]);
            uint32_t a3 = __float_as_uint(Qs[(m0 + gp + 8) * QS_STRIDE + kc + qd + 4]);
            #pragma unroll
            for (int j = 0; j < 4; j++) {
                const int n0 = ng * 32 + j * 8;
                uint32_t b0 = __float_as_uint(Ks[(n0 + gp) * KS_STRIDE + kc + qd]);
                uint32_t b1 = __float_as_uint(Ks[(n0 + gp) * KS_STRIDE + kc + qd + 4]);
                mma_tf32(d[j][0], d[j][1], d[j][2], d[j][3], a0, a1, a2, a3, b0, b1);
            }
        }
        // stage scores to smem (f32 exact)
        #pragma unroll
        for (int j = 0; j < 4; j++) {
            const int n0 = ng * 32 + j * 8;
            *(float2*)&At[(m0 + gp)     * AT_STRIDE + n0 + 2 * qd] = make_float2(d[j][0], d[j][1]);
            *(float2*)&At[(m0 + gp + 8) * AT_STRIDE + n0 + 2 * qd] = make_float2(d[j][2], d[j][3]);
        }
        __syncthreads();

        // ---- Stick-breaking scan: warp owns rows warp*8..+7, lane owns keys lane, lane+32 ----
        #pragma unroll
        for (int r = 0; r < 8; r++) {
            const int row = warp * 8 + r;
            const int tg  = t0 + row;
            const float x0 = At[row * AT_STRIDE + lane];
            const float x1 = At[row * AT_STRIDE + lane + 32];
            const bool mm0 = (s0 + lane)      < tg;
            const bool mm1 = (s0 + lane + 32) < tg;
            float p0 = mm0 ? (fmaxf(x0, 0.f) + __logf(1.f + __expf(-fabsf(x0)))) : 0.f;
            float p1 = mm1 ? (fmaxf(x1, 0.f) + __logf(1.f + __expf(-fabsf(x1)))) : 0.f;

            float i0 = p0, i1 = p1;
            #pragma unroll
            for (int off = 1; off < 32; off <<= 1) {
                float u0 = __shfl_down_sync(0xffffffffu, i0, off);
                float u1 = __shfl_down_sync(0xffffffffu, i1, off);
                if (lane + off < 32) { i0 += u0; i1 += u1; }
            }
            const float tot0 = __shfl_sync(0xffffffffu, i0, 0);
            const float tot1 = __shfl_sync(0xffffffffu, i1, 0);
            const float ex1  = i1 - p1;
            const float ex0  = (i0 - p0) + tot1;
            const float base = run[r];
            const float att0 = mm0 ? __expf(x0 - p0 - base - ex0) : 0.f;
            const float att1 = mm1 ? __expf(x1 - p1 - base - ex1) : 0.f;
            At[row * AT_STRIDE + lane]      = __uint_as_float(f2tf(att0));
            At[row * AT_STRIDE + lane + 32] = __uint_as_float(f2tf(att1));
            run[r] = base + tot0 + tot1;
        }
        __syncthreads();

        // ---- A·V on tensor pipe: O[m][n] += sum_s A[m][s] V[s][n] ----
        #pragma unroll
        for (int ks = 0; ks < 8; ks++) {
            const int kc = ks * 8;
            uint32_t a0 = __float_as_uint(At[(m0 + gp)     * AT_STRIDE + kc + qd]);
            uint32_t a1 = __float_as_uint(At[(m0 + gp + 8) * AT_STRIDE + kc + qd]);
            uint32_t a2 = __float_as_uint(At[(m0 + gp)     * AT_STRIDE + kc + qd + 4]);
            uint32_t a3 = __float_as_uint(At[(m0 + gp + 8) * AT_STRIDE + kc + qd + 4]);
            #pragma unroll
            for (int j = 0; j < 4; j++) {
                const int n0 = ng * 32 + j * 8;
                uint32_t b0 = __float_as_uint(Vs[(kc + qd)     * VS_STRIDE + n0 + gp]);
                uint32_t b1 = __float_as_uint(Vs[(kc + qd + 4) * VS_STRIDE + n0 + gp]);
                mma_tf32(o[j][0], o[j][1], o[j][2], o[j][3], a0, a1, a2, a3, b0, b1);
            }
        }
    }

    // ---- Remainder handoff (scan layout -> mma layout) ----
    if (lane == 0) {
        #pragma unroll
        for (int r = 0; r < 8; r++) RemS[warp * 8 + r] = __expf(-run[r]);
    }
    __syncthreads();

    // ---- Epilogue: out = O + rem * v ----
    const float rema = RemS[m0 + gp];
    const float remb = RemS[m0 + gp + 8];
    const int ra = t0 + m0 + gp;
    const int rb = ra + 8;
    #pragma unroll
    for (int j = 0; j < 4; j++) {
        const int n0 = ng * 32 + j * 8 + 2 * qd;
        const float* vpa = qkv + (((size_t)b * S_LEN + ra) * 3 + 2) * (NH * HD) + h * HD + n0;
        const float* vpb = qkv + (((size_t)b * S_LEN + rb) * 3 + 2) * (NH * HD) + h * HD + n0;
        float2 va = *(const float2*)vpa;
        float2 vb = *(const float2*)vpb;
        float2 oa = make_float2(o[j][0] + rema * va.x, o[j][1] + rema * va.y);
        float2 ob = make_float2(o[j][2] + remb * vb.x, o[j][3] + remb * vb.y);
        *(float2*)(out + (((size_t)b * S_LEN + ra) * NH + h) * HD + n0) = oa;
        *(float2*)(out + (((size_t)b * S_LEN + rb) * NH + h) * HD + n0) = ob;
    }
}

extern "C" void kernel_launch(void* const* d_in, const int* in_sizes, int n_in,
                              void* d_out, int out_size)
{
    const float* qkv = (const float*)d_in[0];
    float* out = (float*)d_out;

    cudaFuncSetAttribute(sb_attn_kernel,
                         cudaFuncAttributeMaxDynamicSharedMemorySize,
                         SMEM_FLOATS * sizeof(float));

    dim3 grid(S_LEN / 64, NH, 2);   // (32, 16, 2)
    dim3 block(NTHR);
    sb_attn_kernel<<<grid, block, SMEM_FLOATS * sizeof(float)>>>(qkv, out);
}